// round 2
// baseline (speedup 1.0000x reference)
#include <cuda_runtime.h>

#define DEF 256
#define NF  4096   // DEF * HEAD
#define BSZ 4096

// Scratch for relu(x @ W + b) activations: [2][4096, 4096] f32 (134 MB).
__device__ float g_att[2][(size_t)BSZ * NF];

__device__ __forceinline__ float tanh_fast(float x) {
    float y;
    asm("tanh.approx.f32 %0, %1;" : "=f"(y) : "f"(x));
    return y;
}

// ---------------------------------------------------------------------------
// Kernel 1: C = relu(A[M,256] @ W[256,4096] + bias), C stored to g_att[zsel].
// 128x128 CTA tile, BK=8, 256 threads, 8x8 per thread (split-4 layout).
// ---------------------------------------------------------------------------
__global__ __launch_bounds__(256) void gemm_relu_kernel(
    const float* __restrict__ A, const float* __restrict__ W,
    const float* __restrict__ bias, int zsel)
{
    __shared__ float As[8][132];   // A tile transposed: As[k][m], padded
    __shared__ float Bs[8][128];   // W tile: Bs[k][n]

    float* __restrict__ C = g_att[zsel];

    const int tid = threadIdx.x;
    const int tm  = tid >> 4;      // 0..15
    const int tn  = tid & 15;      // 0..15
    const int Mb  = blockIdx.y * 128;
    const int Nb  = blockIdx.x * 128;

    // A-tile loader mapping: one float4 per thread per k-step
    const int arow = tid >> 1;            // 0..127
    const int akq  = (tid & 1) * 4;       // 0 or 4
    // W-tile loader mapping
    const int wk = tid >> 5;              // 0..7
    const int wn = (tid & 31) * 4;        // 0..124

    const float* Aptr = A + (size_t)(Mb + arow) * DEF + akq;
    const float* Wptr = W + (size_t)wk * NF + Nb + wn;

    float acc[8][8];
#pragma unroll
    for (int i = 0; i < 8; i++)
#pragma unroll
        for (int j = 0; j < 8; j++) acc[i][j] = 0.0f;

    for (int k0 = 0; k0 < DEF; k0 += 8) {
        float4 av = *(const float4*)(Aptr + k0);
        float4 wv = *(const float4*)(Wptr + (size_t)k0 * NF);
        As[akq + 0][arow] = av.x;
        As[akq + 1][arow] = av.y;
        As[akq + 2][arow] = av.z;
        As[akq + 3][arow] = av.w;
        *(float4*)&Bs[wk][wn] = wv;
        __syncthreads();

#pragma unroll
        for (int kk = 0; kk < 8; kk++) {
            float4 a0 = *(const float4*)&As[kk][tm * 4];
            float4 a1 = *(const float4*)&As[kk][tm * 4 + 64];
            float4 b0 = *(const float4*)&Bs[kk][tn * 4];
            float4 b1 = *(const float4*)&Bs[kk][tn * 4 + 64];
            float a[8] = {a0.x, a0.y, a0.z, a0.w, a1.x, a1.y, a1.z, a1.w};
            float b[8] = {b0.x, b0.y, b0.z, b0.w, b1.x, b1.y, b1.z, b1.w};
#pragma unroll
            for (int i = 0; i < 8; i++)
#pragma unroll
                for (int j = 0; j < 8; j++)
                    acc[i][j] = fmaf(a[i], b[j], acc[i][j]);
        }
        __syncthreads();
    }

    // Epilogue: bias + relu, float4 stores
    float bcol[8];
#pragma unroll
    for (int j = 0; j < 4; j++) {
        bcol[j]     = bias[Nb + tn * 4 + j];
        bcol[4 + j] = bias[Nb + tn * 4 + 64 + j];
    }
#pragma unroll
    for (int i = 0; i < 8; i++) {
        int row = Mb + tm * 4 + (i < 4 ? i : 64 + (i - 4));
        float4 v0, v1;
        v0.x = fmaxf(acc[i][0] + bcol[0], 0.0f);
        v0.y = fmaxf(acc[i][1] + bcol[1], 0.0f);
        v0.z = fmaxf(acc[i][2] + bcol[2], 0.0f);
        v0.w = fmaxf(acc[i][3] + bcol[3], 0.0f);
        v1.x = fmaxf(acc[i][4] + bcol[4], 0.0f);
        v1.y = fmaxf(acc[i][5] + bcol[5], 0.0f);
        v1.z = fmaxf(acc[i][6] + bcol[6], 0.0f);
        v1.w = fmaxf(acc[i][7] + bcol[7], 0.0f);
        *(float4*)&C[(size_t)row * NF + Nb + tn * 4]      = v0;
        *(float4*)&C[(size_t)row * NF + Nb + tn * 4 + 64] = v1;
    }
}

// ---------------------------------------------------------------------------
// Kernel 2: per-sample interaction.
//   D = g_att[0][b] viewed [256,16]  (elem (d,h) at d*16+h)
//   P = g_att[1][b] viewed [16,256]  (elem (h,p) at h*256+p)
//   S = D @ P; t = tanh(S/16); rowsum_d = sum_p t; colsum_p = sum_d t
//   out1[b,d] = drug[b,d]    * tanh(rowsum_d)
//   out2[b,p] = protein[b,p] * tanh(colsum_p)
// 256 threads, 8x8 per thread over four 128x128 quadrants, K=16.
// ---------------------------------------------------------------------------
__global__ __launch_bounds__(256) void interact_kernel(
    const float* __restrict__ drug, const float* __restrict__ protein,
    float* __restrict__ out, int bsz)
{
    __shared__ float Dt[16][260];       // D transposed: Dt[h][d]
    __shared__ float Pm[16][256];       // Pm[h][p]
    __shared__ float colpart[8][256];   // per-warp column partials
    __shared__ float rowsum[256];

    const int b    = blockIdx.x;
    const int tid  = threadIdx.x;
    const int tm   = tid >> 4;
    const int tn   = tid & 15;
    const int w    = tid >> 5;
    const int lane = tid & 31;

    const float4* Dr = (const float4*)(g_att[0] + (size_t)b * NF);
    const float4* Pr = (const float4*)(g_att[1] + (size_t)b * NF);

#pragma unroll
    for (int it = 0; it < 4; it++) {
        int i4 = tid + it * 256;             // float4 index, 0..1023
        float4 dv = Dr[i4];
        int d  = i4 >> 2;
        int hb = (i4 & 3) * 4;
        Dt[hb + 0][d] = dv.x;
        Dt[hb + 1][d] = dv.y;
        Dt[hb + 2][d] = dv.z;
        Dt[hb + 3][d] = dv.w;
        ((float4*)&Pm[0][0])[i4] = Pr[i4];
    }
    __syncthreads();

    float colpA[2][8];
#pragma unroll
    for (int nb = 0; nb < 2; nb++)
#pragma unroll
        for (int j = 0; j < 8; j++) colpA[nb][j] = 0.0f;

#pragma unroll
    for (int mb = 0; mb < 2; mb++) {
        float rowp[8];
#pragma unroll
        for (int i = 0; i < 8; i++) rowp[i] = 0.0f;

#pragma unroll
        for (int nb = 0; nb < 2; nb++) {
            const int rbase = mb * 128 + tm * 4;
            const int cbase = nb * 128 + tn * 4;
            float acc[8][8];
#pragma unroll
            for (int i = 0; i < 8; i++)
#pragma unroll
                for (int j = 0; j < 8; j++) acc[i][j] = 0.0f;

#pragma unroll
            for (int h = 0; h < 16; h++) {
                float4 a0 = *(const float4*)&Dt[h][rbase];
                float4 a1 = *(const float4*)&Dt[h][rbase + 64];
                float4 b0 = *(const float4*)&Pm[h][cbase];
                float4 b1 = *(const float4*)&Pm[h][cbase + 64];
                float a[8] = {a0.x, a0.y, a0.z, a0.w, a1.x, a1.y, a1.z, a1.w};
                float bb[8] = {b0.x, b0.y, b0.z, b0.w, b1.x, b1.y, b1.z, b1.w};
#pragma unroll
                for (int i = 0; i < 8; i++)
#pragma unroll
                    for (int j = 0; j < 8; j++)
                        acc[i][j] = fmaf(a[i], bb[j], acc[i][j]);
            }
#pragma unroll
            for (int i = 0; i < 8; i++)
#pragma unroll
                for (int j = 0; j < 8; j++) {
                    float v = tanh_fast(acc[i][j] * 0.0625f);
                    rowp[i]      += v;
                    colpA[nb][j] += v;
                }
        }

        // Reduce rowp across the 16 tn lanes (same tm)
#pragma unroll
        for (int off = 8; off >= 1; off >>= 1)
#pragma unroll
            for (int i = 0; i < 8; i++)
                rowp[i] += __shfl_xor_sync(0xffffffffu, rowp[i], off);

        if (tn == 0) {
            int rbase = mb * 128 + tm * 4;
#pragma unroll
            for (int i = 0; i < 4; i++) {
                rowsum[rbase + i]      = rowp[i];
                rowsum[rbase + 64 + i] = rowp[4 + i];
            }
        }
    }

    // Merge the two tm's of each warp (lane ^ 16 has same tn), write col partials
#pragma unroll
    for (int nb = 0; nb < 2; nb++) {
#pragma unroll
        for (int j = 0; j < 8; j++)
            colpA[nb][j] += __shfl_xor_sync(0xffffffffu, colpA[nb][j], 16);
        if (lane < 16) {
            int cbase = nb * 128 + tn * 4;
#pragma unroll
            for (int j = 0; j < 4; j++) {
                colpart[w][cbase + j]      = colpA[nb][j];
                colpart[w][cbase + 64 + j] = colpA[nb][4 + j];
            }
        }
    }
    __syncthreads();

    float cs = 0.0f;
#pragma unroll
    for (int i = 0; i < 8; i++) cs += colpart[i][tid];
    float rs = rowsum[tid];

    size_t o = (size_t)b * DEF + tid;
    out[o]                          = drug[o]    * tanhf(rs);
    out[(size_t)bsz * DEF + o]      = protein[o] * tanhf(cs);
}

// ---------------------------------------------------------------------------
extern "C" void kernel_launch(void* const* d_in, const int* in_sizes, int n_in,
                              void* d_out, int out_size)
{
    const float* drug    = (const float*)d_in[0];
    const float* protein = (const float*)d_in[1];
    const float* W_d     = (const float*)d_in[2];
    const float* b_d     = (const float*)d_in[3];
    const float* W_p     = (const float*)d_in[4];
    const float* b_p     = (const float*)d_in[5];
    float* out = (float*)d_out;

    int bsz = in_sizes[0] / DEF;   // 4096

    dim3 grid(NF / 128, bsz / 128);
    gemm_relu_kernel<<<grid, 256>>>(drug,    W_d, b_d, 0);
    gemm_relu_kernel<<<grid, 256>>>(protein, W_p, b_p, 1);
    interact_kernel<<<bsz, 256>>>(drug, protein, out, bsz);
}

// round 4
// speedup vs baseline: 5.6945x; 5.6945x over previous
#include <cuda_runtime.h>
#include <cuda_bf16.h>
#include <cuda_fp16.h>
#include <cstdint>

#define DEF 256
#define NF  4096   // DEF * HEAD
#define BSZ 4096

// bf16 scratch
__device__ __nv_bfloat16 g_abf[2][(size_t)BSZ * DEF];   // drug/protein bf16
__device__ __nv_bfloat16 g_wbf[2][(size_t)NF * DEF];    // W transposed [n][k] bf16 (W_d pre-scaled by 1/16)
__device__ __nv_bfloat16 g_att[2][(size_t)BSZ * NF];    // relu activations bf16 (drug side pre-scaled)

// ---------------------------------------------------------------------------
// helpers
// ---------------------------------------------------------------------------
__device__ __forceinline__ float tanh_fast(float x) {
    float y;
    asm("tanh.approx.f32 %0, %1;" : "=f"(y) : "f"(x));
    return y;
}
__device__ __forceinline__ uint32_t smem_u32(const void* p) {
    uint32_t a;
    asm("{ .reg .u64 t; cvta.to.shared.u64 t, %1; cvt.u32.u64 %0, t; }" : "=r"(a) : "l"(p));
    return a;
}
__device__ __forceinline__ void cp16(uint32_t dst, const void* src) {
    asm volatile("cp.async.cg.shared.global [%0], [%1], 16;"
                 :: "r"(dst), "l"(__cvta_generic_to_global(src)) : "memory");
}
#define CP_COMMIT() asm volatile("cp.async.commit_group;" ::: "memory")
#define CP_WAIT(n)  asm volatile("cp.async.wait_group %0;" :: "n"(n) : "memory")

__device__ __forceinline__ void ldsm_x4(uint32_t (&r)[4], uint32_t addr) {
    asm volatile("ldmatrix.sync.aligned.m8n8.x4.shared.b16 {%0,%1,%2,%3}, [%4];"
                 : "=r"(r[0]), "=r"(r[1]), "=r"(r[2]), "=r"(r[3]) : "r"(addr));
}
__device__ __forceinline__ void ldsm_x4t(uint32_t (&r)[4], uint32_t addr) {
    asm volatile("ldmatrix.sync.aligned.m8n8.x4.trans.shared.b16 {%0,%1,%2,%3}, [%4];"
                 : "=r"(r[0]), "=r"(r[1]), "=r"(r[2]), "=r"(r[3]) : "r"(addr));
}
__device__ __forceinline__ void mma_bf16(float (&d)[4], const uint32_t (&a)[4],
                                         uint32_t b0, uint32_t b1) {
    asm volatile("mma.sync.aligned.m16n8k16.row.col.f32.bf16.bf16.f32 "
                 "{%0,%1,%2,%3}, {%4,%5,%6,%7}, {%8,%9}, {%0,%1,%2,%3};"
                 : "+f"(d[0]), "+f"(d[1]), "+f"(d[2]), "+f"(d[3])
                 : "r"(a[0]), "r"(a[1]), "r"(a[2]), "r"(a[3]), "r"(b0), "r"(b1));
}
// pack (lo, hi) to f16x2 and tanh both halves
__device__ __forceinline__ __half2 pack_tanh(float lo, float hi) {
    uint32_t r;
    asm("{ .reg .b32 t; cvt.rn.f16x2.f32 t, %1, %2; tanh.approx.f16x2 %0, t; }"
        : "=r"(r) : "f"(hi), "f"(lo));
    return *reinterpret_cast<__half2*>(&r);
}
__device__ __forceinline__ __half2 shfl_h2(__half2 v, int m) {
    uint32_t u = *reinterpret_cast<uint32_t*>(&v);
    u = __shfl_xor_sync(0xffffffffu, u, m);
    return *reinterpret_cast<__half2*>(&u);
}

// ---------------------------------------------------------------------------
// Prepass 1: drug/protein fp32 -> bf16
// ---------------------------------------------------------------------------
__global__ __launch_bounds__(256) void aconv_kernel(const float* __restrict__ drug,
                                                    const float* __restrict__ protein)
{
    int i = blockIdx.x * 256 + threadIdx.x;           // < BSZ*DEF/4
    float4 v = ((const float4*)drug)[i];
    __nv_bfloat162* d0 = (__nv_bfloat162*)g_abf[0];
    d0[i * 2]     = __float22bfloat162_rn(make_float2(v.x, v.y));
    d0[i * 2 + 1] = __float22bfloat162_rn(make_float2(v.z, v.w));
    float4 w = ((const float4*)protein)[i];
    __nv_bfloat162* d1 = (__nv_bfloat162*)g_abf[1];
    d1[i * 2]     = __float22bfloat162_rn(make_float2(w.x, w.y));
    d1[i * 2 + 1] = __float22bfloat162_rn(make_float2(w.z, w.w));
}

// ---------------------------------------------------------------------------
// Prepass 2: transpose + convert W[k][n] -> Wt[n][k] bf16; W_d scaled by 1/16
// ---------------------------------------------------------------------------
__global__ __launch_bounds__(256) void wconv_kernel(const float* __restrict__ Wd,
                                                    const float* __restrict__ Wp)
{
    __shared__ float t[32][33];
    int z = blockIdx.z;
    const float* W = z ? Wp : Wd;
    float scale = z ? 1.0f : 0.0625f;
    int n0 = blockIdx.x * 32, k0 = blockIdx.y * 32;
    int tx = threadIdx.x, ty = threadIdx.y;           // (32, 8)
#pragma unroll
    for (int r = 0; r < 4; r++)
        t[ty + r * 8][tx] = W[(size_t)(k0 + ty + r * 8) * NF + n0 + tx];
    __syncthreads();
#pragma unroll
    for (int r = 0; r < 4; r++)
        g_wbf[z][(size_t)(n0 + ty + r * 8) * DEF + k0 + tx] =
            __float2bfloat16(t[tx][ty + r * 8] * scale);
}

// ---------------------------------------------------------------------------
// HMMA GEMM: g_att[z][128x128 tile] = relu(A[128x256] @ Wt^T + bias)
// 256 thr (8 warps, warp tile 64x32), K in 2 chunks of 128, cp.async 2-stage.
// ---------------------------------------------------------------------------
#define GSMEM 131072

__global__ __launch_bounds__(256) void gemm_tc_kernel(const float* __restrict__ b_d,
                                                      const float* __restrict__ b_p)
{
    extern __shared__ __align__(16) char dsm[];       // A0|A1|B0|B1 32KB each
    __shared__ float bias_s[128];

    const int tid = threadIdx.x, lane = tid & 31, w = tid >> 5;
    const int wm = w >> 2, wn = w & 3;                // 2x4 warp grid
    const int Nb = blockIdx.x * 128, Mb = blockIdx.y * 128, z = blockIdx.z;
    uint32_t sbase = smem_u32(dsm);

    const __nv_bfloat16* Ag = g_abf[z];
    const __nv_bfloat16* Bg = g_wbf[z];
    if (tid < 128) bias_s[tid] = (z ? b_p[Nb + tid] : b_d[Nb + tid] * 0.0625f);

    // stage both K-chunks (one commit group per chunk)
#pragma unroll
    for (int ch = 0; ch < 2; ch++) {
#pragma unroll
        for (int j = 0; j < 8; j++) {
            int idx = tid + j * 256;                   // 0..2047
            int r = idx >> 4, c = idx & 15;
            uint32_t sw = (uint32_t)(r * 256 + ((c ^ (r & 7)) << 4));
            cp16(sbase + ch * 32768 + sw,
                 Ag + (size_t)(Mb + r) * DEF + ch * 128 + c * 8);
            cp16(sbase + 65536 + ch * 32768 + sw,
                 Bg + (size_t)(Nb + r) * DEF + ch * 128 + c * 8);
        }
        CP_COMMIT();
    }

    float acc[4][4][4];
#pragma unroll
    for (int mf = 0; mf < 4; mf++)
#pragma unroll
        for (int nf = 0; nf < 4; nf++)
#pragma unroll
            for (int q = 0; q < 4; q++) acc[mf][nf][q] = 0.0f;

#pragma unroll
    for (int ch = 0; ch < 2; ch++) {
        if (ch == 0) { CP_WAIT(1); } else { CP_WAIT(0); }
        __syncthreads();
        uint32_t aBase = sbase + ch * 32768;
        uint32_t bBase = sbase + 65536 + ch * 32768;
#pragma unroll
        for (int ks = 0; ks < 8; ks++) {
            uint32_t a[4][4];
#pragma unroll
            for (int mf = 0; mf < 4; mf++) {
                int m0 = wm * 64 + mf * 16;
                int r  = m0 + (lane & 7) + 8 * ((lane >> 3) & 1);
                int kc = ks * 2 + (lane >> 4);
                ldsm_x4(a[mf], aBase + r * 256 + ((kc ^ (r & 7)) << 4));
            }
            uint32_t bq[2][4];
#pragma unroll
            for (int g = 0; g < 2; g++) {
                int n0 = wn * 32 + g * 16;
                int nr = n0 + (lane & 7) + 8 * ((lane >> 4) & 1);
                int kc = ks * 2 + ((lane >> 3) & 1);
                ldsm_x4(bq[g], bBase + nr * 256 + ((kc ^ (nr & 7)) << 4));
            }
#pragma unroll
            for (int mf = 0; mf < 4; mf++)
#pragma unroll
                for (int nf = 0; nf < 4; nf++)
                    mma_bf16(acc[mf][nf], a[mf],
                             bq[nf >> 1][(nf & 1) * 2], bq[nf >> 1][(nf & 1) * 2 + 1]);
        }
    }

    // epilogue: bias + relu -> bf16
#pragma unroll
    for (int mf = 0; mf < 4; mf++) {
        int row0 = Mb + wm * 64 + mf * 16 + (lane >> 2);
#pragma unroll
        for (int nf = 0; nf < 4; nf++) {
            int colL = wn * 32 + nf * 8 + 2 * (lane & 3);
            float bi0 = bias_s[colL], bi1 = bias_s[colL + 1];
            float f0 = fmaxf(acc[mf][nf][0] + bi0, 0.0f);
            float f1 = fmaxf(acc[mf][nf][1] + bi1, 0.0f);
            float f2 = fmaxf(acc[mf][nf][2] + bi0, 0.0f);
            float f3 = fmaxf(acc[mf][nf][3] + bi1, 0.0f);
            __nv_bfloat162 p0 = __float22bfloat162_rn(make_float2(f0, f1));
            __nv_bfloat162 p1 = __float22bfloat162_rn(make_float2(f2, f3));
            *reinterpret_cast<uint32_t*>(&g_att[z][(size_t)row0 * NF + Nb + colL]) =
                *reinterpret_cast<uint32_t*>(&p0);
            *reinterpret_cast<uint32_t*>(&g_att[z][(size_t)(row0 + 8) * NF + Nb + colL]) =
                *reinterpret_cast<uint32_t*>(&p1);
        }
    }
}

// ---------------------------------------------------------------------------
// Interaction: per-sample S = D(scaled) @ P via HMMA (K=16), tanh in f16x2,
// packed row/col accumulation, final out = input * tanh(sum).
// ---------------------------------------------------------------------------
__global__ __launch_bounds__(256) void interact_kernel(
    const float* __restrict__ drug, const float* __restrict__ protein,
    float* __restrict__ out)
{
    __shared__ __align__(16) char Dsm[256 * 48];      // D rows stride 48B (32B data + pad)
    __shared__ __align__(16) char Psm[16 * 512];      // P [16][256] bf16, XOR-swizzled
    __shared__ __half2 colpart[8][128];               // per-warp 32-row col-pair sums
    __shared__ float rowsum[256];

    const int b = blockIdx.x, tid = threadIdx.x, lane = tid & 31, w = tid >> 5;
    uint32_t sD = smem_u32(Dsm), sP = smem_u32(Psm);
    const __nv_bfloat16* Drow = g_att[0] + (size_t)b * NF;
    const __nv_bfloat16* Prow = g_att[1] + (size_t)b * NF;

#pragma unroll
    for (int j = 0; j < 2; j++) {
        int idx = tid + j * 256;                       // 0..511, 16B chunks
        int r = idx >> 1, c = idx & 1;
        cp16(sD + r * 48 + c * 16, Drow + idx * 8);
        int h = idx >> 5, c2 = idx & 31;
        cp16(sP + h * 512 + ((c2 ^ (h & 7)) << 4), Prow + idx * 8);
    }
    CP_COMMIT(); CP_WAIT(0); __syncthreads();

    // A-frags for this warp's 32 rows
    uint32_t a[2][4];
#pragma unroll
    for (int mf = 0; mf < 2; mf++) {
        int m0 = w * 32 + mf * 16;
        int r  = m0 + (lane & 7) + 8 * ((lane >> 3) & 1);
        int kc = lane >> 4;
        ldsm_x4(a[mf], sD + r * 48 + kc * 16);
    }

    __half2 zero2 = __float2half2_rn(0.0f);
    __half2 rowp[4] = {zero2, zero2, zero2, zero2};    // (mf, rowhalf)

#pragma unroll
    for (int it = 0; it < 16; it++) {
        int n0 = it * 16;
        uint32_t bq[4];
        {
            int h = (lane & 7) + 8 * ((lane >> 3) & 1);
            int n = n0 + 8 * (lane >> 4);
            ldsm_x4t(bq, sP + h * 512 + ((((n) >> 3) ^ (h & 7)) << 4));
        }
        __half2 cp0 = zero2, cp1 = zero2;
#pragma unroll
        for (int mf = 0; mf < 2; mf++) {
            float d0[4] = {0.f, 0.f, 0.f, 0.f};
            mma_bf16(d0, a[mf], bq[0], bq[1]);         // cols n0 + 2q
            __half2 tA = pack_tanh(d0[0], d0[1]);
            __half2 tB = pack_tanh(d0[2], d0[3]);
            rowp[mf * 2 + 0] = __hadd2(rowp[mf * 2 + 0], tA);
            rowp[mf * 2 + 1] = __hadd2(rowp[mf * 2 + 1], tB);
            cp0 = __hadd2(cp0, __hadd2(tA, tB));

            float d1[4] = {0.f, 0.f, 0.f, 0.f};
            mma_bf16(d1, a[mf], bq[2], bq[3]);         // cols n0 + 8 + 2q
            tA = pack_tanh(d1[0], d1[1]);
            tB = pack_tanh(d1[2], d1[3]);
            rowp[mf * 2 + 0] = __hadd2(rowp[mf * 2 + 0], tA);
            rowp[mf * 2 + 1] = __hadd2(rowp[mf * 2 + 1], tB);
            cp1 = __hadd2(cp1, __hadd2(tA, tB));
        }
        // reduce col pairs across t%4 classes (bits 2..4)
        cp0 = __hadd2(cp0, shfl_h2(cp0, 4));
        cp0 = __hadd2(cp0, shfl_h2(cp0, 8));
        cp0 = __hadd2(cp0, shfl_h2(cp0, 16));
        cp1 = __hadd2(cp1, shfl_h2(cp1, 4));
        cp1 = __hadd2(cp1, shfl_h2(cp1, 8));
        cp1 = __hadd2(cp1, shfl_h2(cp1, 16));
        if (lane < 4) {
            colpart[w][(n0 >> 1) + lane]     = cp0;
            colpart[w][(n0 >> 1) + 4 + lane] = cp1;
        }
    }

    // row sums: reduce across the 4 lanes of each quad
#pragma unroll
    for (int s = 0; s < 4; s++) {
        __half2 v = rowp[s];
        v = __hadd2(v, shfl_h2(v, 1));
        v = __hadd2(v, shfl_h2(v, 2));
        if ((lane & 3) == 0) {
            int row = w * 32 + (s >> 1) * 16 + (s & 1) * 8 + (lane >> 2);
            rowsum[row] = __low2float(v) + __high2float(v);
        }
    }
    __syncthreads();

    size_t o = (size_t)b * DEF + tid;
    out[o] = drug[o] * tanh_fast(rowsum[tid]);

    if (tid < 128) {
        float c0 = 0.0f, c1 = 0.0f;
#pragma unroll
        for (int ww = 0; ww < 8; ww++) {
            __half2 v = colpart[ww][tid];
            c0 += __low2float(v);
            c1 += __high2float(v);
        }
        size_t base2 = (size_t)BSZ * DEF + (size_t)b * DEF + 2 * tid;
        out[base2]     = protein[(size_t)b * DEF + 2 * tid]     * tanh_fast(c0);
        out[base2 + 1] = protein[(size_t)b * DEF + 2 * tid + 1] * tanh_fast(c1);
    }
}

// ---------------------------------------------------------------------------
extern "C" void kernel_launch(void* const* d_in, const int* in_sizes, int n_in,
                              void* d_out, int out_size)
{
    const float* drug    = (const float*)d_in[0];
    const float* protein = (const float*)d_in[1];
    const float* W_d     = (const float*)d_in[2];
    const float* b_d     = (const float*)d_in[3];
    const float* W_p     = (const float*)d_in[4];
    const float* b_p     = (const float*)d_in[5];
    float* out = (float*)d_out;

    cudaFuncSetAttribute(gemm_tc_kernel, cudaFuncAttributeMaxDynamicSharedMemorySize, GSMEM);

    aconv_kernel<<<BSZ * DEF / 4 / 256, 256>>>(drug, protein);
    wconv_kernel<<<dim3(NF / 32, DEF / 32, 2), dim3(32, 8)>>>(W_d, W_p);
    gemm_tc_kernel<<<dim3(NF / 128, BSZ / 128, 2), 256, GSMEM>>>(b_d, b_p);
    interact_kernel<<<BSZ, 256>>>(drug, protein, out);
}

// round 6
// speedup vs baseline: 6.3748x; 1.1195x over previous
#include <cuda_runtime.h>
#include <cuda_fp16.h>
#include <cstdint>

#define DEF 256
#define NF  4096   // DEF * HEAD
#define BSZ 4096

// f16 scratch
__device__ __half g_abf[2][(size_t)BSZ * DEF];   // drug/protein f16
__device__ __half g_wbf[2][(size_t)NF * DEF];    // W transposed [n][k] f16 (W_d pre-scaled by 1/16)
__device__ __half g_att[2][(size_t)BSZ * NF];    // relu activations f16 (drug side pre-scaled)

// ---------------------------------------------------------------------------
// helpers
// ---------------------------------------------------------------------------
__device__ __forceinline__ float tanh_fast(float x) {
    float y;
    asm("tanh.approx.f32 %0, %1;" : "=f"(y) : "f"(x));
    return y;
}
__device__ __forceinline__ __half2 tanh_h2(uint32_t v) {
    uint32_t r;
    asm("tanh.approx.f16x2 %0, %1;" : "=r"(r) : "r"(v));
    return *reinterpret_cast<__half2*>(&r);
}
__device__ __forceinline__ uint32_t smem_u32(const void* p) {
    uint32_t a;
    asm("{ .reg .u64 t; cvta.to.shared.u64 t, %1; cvt.u32.u64 %0, t; }" : "=r"(a) : "l"(p));
    return a;
}
__device__ __forceinline__ void cp16(uint32_t dst, const void* src) {
    asm volatile("cp.async.cg.shared.global [%0], [%1], 16;"
                 :: "r"(dst), "l"(__cvta_generic_to_global(src)) : "memory");
}
#define CP_COMMIT() asm volatile("cp.async.commit_group;" ::: "memory")
#define CP_WAIT(n)  asm volatile("cp.async.wait_group %0;" :: "n"(n) : "memory")

__device__ __forceinline__ void ldsm_x4(uint32_t (&r)[4], uint32_t addr) {
    asm volatile("ldmatrix.sync.aligned.m8n8.x4.shared.b16 {%0,%1,%2,%3}, [%4];"
                 : "=r"(r[0]), "=r"(r[1]), "=r"(r[2]), "=r"(r[3]) : "r"(addr));
}
__device__ __forceinline__ void ldsm_x4t(uint32_t (&r)[4], uint32_t addr) {
    asm volatile("ldmatrix.sync.aligned.m8n8.x4.trans.shared.b16 {%0,%1,%2,%3}, [%4];"
                 : "=r"(r[0]), "=r"(r[1]), "=r"(r[2]), "=r"(r[3]) : "r"(addr));
}
// f16 inputs, f32 accumulator (GEMM)
__device__ __forceinline__ void mma_f32(float (&d)[4], const uint32_t (&a)[4],
                                        uint32_t b0, uint32_t b1) {
    asm volatile("mma.sync.aligned.m16n8k16.row.col.f32.f16.f16.f32 "
                 "{%0,%1,%2,%3}, {%4,%5,%6,%7}, {%8,%9}, {%0,%1,%2,%3};"
                 : "+f"(d[0]), "+f"(d[1]), "+f"(d[2]), "+f"(d[3])
                 : "r"(a[0]), "r"(a[1]), "r"(a[2]), "r"(a[3]), "r"(b0), "r"(b1));
}
// f16 inputs, f16 accumulator (interact) — output already packed f16x2
__device__ __forceinline__ void mma_h16(uint32_t (&d)[2], const uint32_t (&a)[4],
                                        uint32_t b0, uint32_t b1) {
    asm volatile("mma.sync.aligned.m16n8k16.row.col.f16.f16.f16.f16 "
                 "{%0,%1}, {%2,%3,%4,%5}, {%6,%7}, {%8,%9};"
                 : "=r"(d[0]), "=r"(d[1])
                 : "r"(a[0]), "r"(a[1]), "r"(a[2]), "r"(a[3]),
                   "r"(b0), "r"(b1), "r"(0u), "r"(0u));
}
__device__ __forceinline__ __half2 shfl_h2(__half2 v, int m) {
    uint32_t u = *reinterpret_cast<uint32_t*>(&v);
    u = __shfl_xor_sync(0xffffffffu, u, m);
    return *reinterpret_cast<__half2*>(&u);
}

// ---------------------------------------------------------------------------
// Prep: blocks [0,1024): drug/protein fp32 -> f16
//       blocks [1024,3072): W[k][n] fp32 -> Wt[n][k] f16 (W_d scaled by 1/16)
// ---------------------------------------------------------------------------
__global__ __launch_bounds__(256) void prep_kernel(
    const float* __restrict__ drug, const float* __restrict__ protein,
    const float* __restrict__ Wd, const float* __restrict__ Wp)
{
    __shared__ float t[32][33];
    int bid = blockIdx.x, tid = threadIdx.x;
    if (bid < 1024) {
        int i = bid * 256 + tid;                      // < BSZ*DEF/4
        float4 v = ((const float4*)drug)[i];
        __half2* d0 = (__half2*)g_abf[0];
        d0[i * 2]     = __floats2half2_rn(v.x, v.y);
        d0[i * 2 + 1] = __floats2half2_rn(v.z, v.w);
        float4 w = ((const float4*)protein)[i];
        __half2* d1 = (__half2*)g_abf[1];
        d1[i * 2]     = __floats2half2_rn(w.x, w.y);
        d1[i * 2 + 1] = __floats2half2_rn(w.z, w.w);
        return;
    }
    int wb = bid - 1024;                              // 0..2047
    int z = wb >> 10;
    int r = wb & 1023;
    int n0 = (r & 127) * 32, k0 = (r >> 7) * 32;
    const float* W = z ? Wp : Wd;
    float scale = z ? 1.0f : 0.0625f;
    int tx = tid & 31, ty = tid >> 5;                 // (32, 8)
#pragma unroll
    for (int q = 0; q < 4; q++)
        t[ty + q * 8][tx] = W[(size_t)(k0 + ty + q * 8) * NF + n0 + tx];
    __syncthreads();
#pragma unroll
    for (int q = 0; q < 4; q++)
        g_wbf[z][(size_t)(n0 + ty + q * 8) * DEF + k0 + tx] =
            __float2half(t[tx][ty + q * 8] * scale);
}

// ---------------------------------------------------------------------------
// HMMA GEMM: g_att[z][128x128 tile] = relu(A[128x256] @ Wt^T + bias)
// 256 thr (8 warps, warp tile 64x32). K = 4 chunks of 64, 2-stage cp.async
// pipeline, 64KB smem -> 2 CTAs/SM. Epilogue staged through smem (STG.128).
// ---------------------------------------------------------------------------
#define GSMEM 65536   // 2 stages x (A 16KB + B 16KB); stage0 reused for C (32KB)

__global__ __launch_bounds__(256, 2) void gemm_tc_kernel(const float* __restrict__ b_d,
                                                         const float* __restrict__ b_p)
{
    extern __shared__ __align__(16) char dsm[];       // stage s: A @ s*32768, B @ s*32768+16384
    __shared__ float bias_s[128];

    const int tid = threadIdx.x, lane = tid & 31, w = tid >> 5;
    const int wm = w >> 2, wn = w & 3;                // 2x4 warp grid
    const int Nb = blockIdx.x * 128, Mb = blockIdx.y * 128, z = blockIdx.z;
    uint32_t sbase = smem_u32(dsm);

    const __half* Ag = g_abf[z];
    const __half* Bg = g_wbf[z];
    if (tid < 128) bias_s[tid] = (z ? b_p[Nb + tid] : b_d[Nb + tid] * 0.0625f);

    // chunk loader: chunk ch (k = ch*64..+64) into stage st
    auto load_chunk = [&](int ch, int st) {
        uint32_t aB = sbase + st * 32768;
        uint32_t bB = aB + 16384;
#pragma unroll
        for (int j = 0; j < 4; j++) {
            int idx = tid + j * 256;                   // 0..1023
            int r = idx >> 3, c = idx & 7;
            uint32_t sw = (uint32_t)(r * 128 + ((c ^ (r & 7)) << 4));
            cp16(aB + sw, Ag + (size_t)(Mb + r) * DEF + ch * 64 + c * 8);
            cp16(bB + sw, Bg + (size_t)(Nb + r) * DEF + ch * 64 + c * 8);
        }
        CP_COMMIT();
    };

    load_chunk(0, 0);
    load_chunk(1, 1);

    float acc[4][4][4];
#pragma unroll
    for (int mf = 0; mf < 4; mf++)
#pragma unroll
        for (int nf = 0; nf < 4; nf++)
#pragma unroll
            for (int q = 0; q < 4; q++) acc[mf][nf][q] = 0.0f;

#pragma unroll
    for (int ch = 0; ch < 4; ch++) {
        if (ch == 3) { CP_WAIT(0); } else { CP_WAIT(1); }
        __syncthreads();
        uint32_t aBase = sbase + (ch & 1) * 32768;
        uint32_t bBase = aBase + 16384;
#pragma unroll
        for (int ks = 0; ks < 4; ks++) {
            uint32_t a[4][4];
#pragma unroll
            for (int mf = 0; mf < 4; mf++) {
                int r  = wm * 64 + mf * 16 + (lane & 7) + 8 * ((lane >> 3) & 1);
                int kc = ks * 2 + (lane >> 4);
                ldsm_x4(a[mf], aBase + r * 128 + ((kc ^ (r & 7)) << 4));
            }
            uint32_t bq[2][4];
#pragma unroll
            for (int g = 0; g < 2; g++) {
                int nr = wn * 32 + g * 16 + (lane & 7) + 8 * ((lane >> 4) & 1);
                int kc = ks * 2 + ((lane >> 3) & 1);
                ldsm_x4(bq[g], bBase + nr * 128 + ((kc ^ (nr & 7)) << 4));
            }
#pragma unroll
            for (int mf = 0; mf < 4; mf++)
#pragma unroll
                for (int nf = 0; nf < 4; nf++)
                    mma_f32(acc[mf][nf], a[mf],
                            bq[nf >> 1][(nf & 1) * 2], bq[nf >> 1][(nf & 1) * 2 + 1]);
        }
        __syncthreads();
        if (ch + 2 < 4) load_chunk(ch + 2, ch & 1);
    }

    // epilogue: bias + relu -> f16, staged via smem (XOR-swizzled), STG.128
#pragma unroll
    for (int mf = 0; mf < 4; mf++) {
        int r0 = wm * 64 + mf * 16 + (lane >> 2);
#pragma unroll
        for (int nf = 0; nf < 4; nf++) {
            int u = wn * 4 + nf;                       // 16B unit within 256B row
            float bi0 = bias_s[u * 8 + 2 * (lane & 3)];
            float bi1 = bias_s[u * 8 + 2 * (lane & 3) + 1];
            __half2 h0 = __floats2half2_rn(fmaxf(acc[mf][nf][0] + bi0, 0.0f),
                                           fmaxf(acc[mf][nf][1] + bi1, 0.0f));
            __half2 h1 = __floats2half2_rn(fmaxf(acc[mf][nf][2] + bi0, 0.0f),
                                           fmaxf(acc[mf][nf][3] + bi1, 0.0f));
            uint32_t a0 = sbase + r0 * 256 + ((u ^ (r0 & 7)) << 4) + 4 * (lane & 3);
            int r1 = r0 + 8;
            uint32_t a1 = sbase + r1 * 256 + ((u ^ (r1 & 7)) << 4) + 4 * (lane & 3);
            asm volatile("st.shared.b32 [%0], %1;" :: "r"(a0), "r"(*(uint32_t*)&h0) : "memory");
            asm volatile("st.shared.b32 [%0], %1;" :: "r"(a1), "r"(*(uint32_t*)&h1) : "memory");
        }
    }
    __syncthreads();
#pragma unroll
    for (int p = 0; p < 8; p++) {
        int g = tid + p * 256;                         // 0..2047 16B units
        int row = g >> 4, u = g & 15;
        uint4 v;
        uint32_t ad = sbase + row * 256 + ((u ^ (row & 7)) << 4);
        asm volatile("ld.shared.v4.u32 {%0,%1,%2,%3}, [%4];"
                     : "=r"(v.x), "=r"(v.y), "=r"(v.z), "=r"(v.w) : "r"(ad));
        *(uint4*)&g_att[z][(size_t)(Mb + row) * NF + Nb + u * 8] = v;
    }
}

// ---------------------------------------------------------------------------
// Interaction: per-sample S = D(scaled) @ P via f16-accumulator HMMA (K=16).
// Accumulator is already f16x2 -> tanh.approx.f16x2 directly (no CVT).
// ---------------------------------------------------------------------------
__global__ __launch_bounds__(256) void interact_kernel(
    const float* __restrict__ drug, const float* __restrict__ protein,
    float* __restrict__ out)
{
    __shared__ __align__(16) char Dsm[256 * 48];      // D rows stride 48B (32B data + pad)
    __shared__ __align__(16) char Psm[16 * 512];      // P [16][256] f16, XOR-swizzled
    __shared__ __half2 colpart[8][128];
    __shared__ float rowsum[256];

    const int b = blockIdx.x, tid = threadIdx.x, lane = tid & 31, w = tid >> 5;
    uint32_t sD = smem_u32(Dsm), sP = smem_u32(Psm);
    const __half* Drow = g_att[0] + (size_t)b * NF;
    const __half* Prow = g_att[1] + (size_t)b * NF;

#pragma unroll
    for (int j = 0; j < 2; j++) {
        int idx = tid + j * 256;                       // 0..511, 16B chunks
        int r = idx >> 1, c = idx & 1;
        cp16(sD + r * 48 + c * 16, Drow + idx * 8);
        int h = idx >> 5, c2 = idx & 31;
        cp16(sP + h * 512 + ((c2 ^ (h & 7)) << 4), Prow + idx * 8);
    }
    CP_COMMIT(); CP_WAIT(0); __syncthreads();

    // A-frags for this warp's 32 rows
    uint32_t a[2][4];
#pragma unroll
    for (int mf = 0; mf < 2; mf++) {
        int r  = w * 32 + mf * 16 + (lane & 7) + 8 * ((lane >> 3) & 1);
        int kc = lane >> 4;
        ldsm_x4(a[mf], sD + r * 48 + kc * 16);
    }

    __half2 zero2 = __float2half2_rn(0.0f);
    __half2 rowp[4] = {zero2, zero2, zero2, zero2};

#pragma unroll
    for (int it = 0; it < 16; it++) {
        int n0 = it * 16;
        uint32_t bq[4];
        {
            int h = (lane & 7) + 8 * ((lane >> 3) & 1);
            int n = n0 + 8 * (lane >> 4);
            ldsm_x4t(bq, sP + h * 512 + (((n >> 3) ^ (h & 7)) << 4));
        }
        __half2 cp0 = zero2, cp1 = zero2;
#pragma unroll
        for (int mf = 0; mf < 2; mf++) {
            uint32_t d0[2];
            mma_h16(d0, a[mf], bq[0], bq[1]);          // cols n0 + 2q
            __half2 tA = tanh_h2(d0[0]);
            __half2 tB = tanh_h2(d0[1]);
            rowp[mf * 2 + 0] = __hadd2(rowp[mf * 2 + 0], tA);
            rowp[mf * 2 + 1] = __hadd2(rowp[mf * 2 + 1], tB);
            cp0 = __hadd2(cp0, __hadd2(tA, tB));

            uint32_t d1[2];
            mma_h16(d1, a[mf], bq[2], bq[3]);          // cols n0 + 8 + 2q
            tA = tanh_h2(d1[0]);
            tB = tanh_h2(d1[1]);
            rowp[mf * 2 + 0] = __hadd2(rowp[mf * 2 + 0], tA);
            rowp[mf * 2 + 1] = __hadd2(rowp[mf * 2 + 1], tB);
            cp1 = __hadd2(cp1, __hadd2(tA, tB));
        }
        cp0 = __hadd2(cp0, shfl_h2(cp0, 4));
        cp0 = __hadd2(cp0, shfl_h2(cp0, 8));
        cp0 = __hadd2(cp0, shfl_h2(cp0, 16));
        cp1 = __hadd2(cp1, shfl_h2(cp1, 4));
        cp1 = __hadd2(cp1, shfl_h2(cp1, 8));
        cp1 = __hadd2(cp1, shfl_h2(cp1, 16));
        if (lane < 4) {
            colpart[w][(n0 >> 1) + lane]     = cp0;
            colpart[w][(n0 >> 1) + 4 + lane] = cp1;
        }
    }

    // row sums: reduce across the 4 lanes of each quad
#pragma unroll
    for (int s = 0; s < 4; s++) {
        __half2 v = rowp[s];
        v = __hadd2(v, shfl_h2(v, 1));
        v = __hadd2(v, shfl_h2(v, 2));
        if ((lane & 3) == 0) {
            int row = w * 32 + (s >> 1) * 16 + (s & 1) * 8 + (lane >> 2);
            rowsum[row] = __low2float(v) + __high2float(v);
        }
    }
    __syncthreads();

    size_t o = (size_t)b * DEF + tid;
    out[o] = drug[o] * tanh_fast(rowsum[tid]);

    if (tid < 128) {
        float c0 = 0.0f, c1 = 0.0f;
#pragma unroll
        for (int ww = 0; ww < 8; ww++) {
            __half2 v = colpart[ww][tid];
            c0 += __low2float(v);
            c1 += __high2float(v);
        }
        size_t base2 = (size_t)BSZ * DEF + (size_t)b * DEF + 2 * tid;
        out[base2]     = protein[(size_t)b * DEF + 2 * tid]     * tanh_fast(c0);
        out[base2 + 1] = protein[(size_t)b * DEF + 2 * tid + 1] * tanh_fast(c1);
    }
}

// ---------------------------------------------------------------------------
extern "C" void kernel_launch(void* const* d_in, const int* in_sizes, int n_in,
                              void* d_out, int out_size)
{
    const float* drug    = (const float*)d_in[0];
    const float* protein = (const float*)d_in[1];
    const float* W_d     = (const float*)d_in[2];
    const float* b_d     = (const float*)d_in[3];
    const float* W_p     = (const float*)d_in[4];
    const float* b_p     = (const float*)d_in[5];
    float* out = (float*)d_out;

    cudaFuncSetAttribute(gemm_tc_kernel, cudaFuncAttributeMaxDynamicSharedMemorySize, GSMEM);

    prep_kernel<<<3072, 256>>>(drug, protein, W_d, W_p);
    gemm_tc_kernel<<<dim3(NF / 128, BSZ / 128, 2), 256, GSMEM>>>(b_d, b_p);
    interact_kernel<<<BSZ, 256>>>(drug, protein, out);
}

// round 7
// speedup vs baseline: 6.5459x; 1.0268x over previous
#include <cuda_runtime.h>
#include <cuda_fp16.h>
#include <cstdint>

#define DEF 256
#define NF  4096   // DEF * HEAD
#define BSZ 4096

// f16 scratch
__device__ __half g_abf[2][(size_t)BSZ * DEF];   // drug/protein f16
__device__ __half g_wbf[2][(size_t)NF * DEF];    // W transposed [n][k] f16 (W_d pre-scaled by 1/16)
__device__ __half g_att[2][(size_t)BSZ * NF];    // relu activations f16 (drug side pre-scaled)

// ---------------------------------------------------------------------------
// helpers
// ---------------------------------------------------------------------------
__device__ __forceinline__ float tanh_fast(float x) {
    float y;
    asm("tanh.approx.f32 %0, %1;" : "=f"(y) : "f"(x));
    return y;
}
__device__ __forceinline__ __half2 tanh_h2(uint32_t v) {
    uint32_t r;
    asm("tanh.approx.f16x2 %0, %1;" : "=r"(r) : "r"(v));
    return *reinterpret_cast<__half2*>(&r);
}
__device__ __forceinline__ uint32_t smem_u32(const void* p) {
    uint32_t a;
    asm("{ .reg .u64 t; cvta.to.shared.u64 t, %1; cvt.u32.u64 %0, t; }" : "=r"(a) : "l"(p));
    return a;
}
__device__ __forceinline__ void cp16(uint32_t dst, const void* src) {
    asm volatile("cp.async.cg.shared.global [%0], [%1], 16;"
                 :: "r"(dst), "l"(__cvta_generic_to_global(src)) : "memory");
}
#define CP_COMMIT() asm volatile("cp.async.commit_group;" ::: "memory")
#define CP_WAIT(n)  asm volatile("cp.async.wait_group %0;" :: "n"(n) : "memory")

__device__ __forceinline__ void ldsm_x4(uint32_t (&r)[4], uint32_t addr) {
    asm volatile("ldmatrix.sync.aligned.m8n8.x4.shared.b16 {%0,%1,%2,%3}, [%4];"
                 : "=r"(r[0]), "=r"(r[1]), "=r"(r[2]), "=r"(r[3]) : "r"(addr));
}
__device__ __forceinline__ void ldsm_x4t(uint32_t (&r)[4], uint32_t addr) {
    asm volatile("ldmatrix.sync.aligned.m8n8.x4.trans.shared.b16 {%0,%1,%2,%3}, [%4];"
                 : "=r"(r[0]), "=r"(r[1]), "=r"(r[2]), "=r"(r[3]) : "r"(addr));
}
// f16 inputs, f16 accumulator, D += A*B (GEMM; 2x HMMA rate vs f32 acc)
__device__ __forceinline__ void mma_h16_acc(uint32_t (&d)[2], const uint32_t (&a)[4],
                                            uint32_t b0, uint32_t b1) {
    asm volatile("mma.sync.aligned.m16n8k16.row.col.f16.f16.f16.f16 "
                 "{%0,%1}, {%2,%3,%4,%5}, {%6,%7}, {%0,%1};"
                 : "+r"(d[0]), "+r"(d[1])
                 : "r"(a[0]), "r"(a[1]), "r"(a[2]), "r"(a[3]), "r"(b0), "r"(b1));
}
// f16 inputs, f16 accumulator, D = A*B (interact)
__device__ __forceinline__ void mma_h16(uint32_t (&d)[2], const uint32_t (&a)[4],
                                        uint32_t b0, uint32_t b1) {
    asm volatile("mma.sync.aligned.m16n8k16.row.col.f16.f16.f16.f16 "
                 "{%0,%1}, {%2,%3,%4,%5}, {%6,%7}, {%8,%9};"
                 : "=r"(d[0]), "=r"(d[1])
                 : "r"(a[0]), "r"(a[1]), "r"(a[2]), "r"(a[3]),
                   "r"(b0), "r"(b1), "r"(0u), "r"(0u));
}
__device__ __forceinline__ __half2 shfl_h2(__half2 v, int m) {
    uint32_t u = *reinterpret_cast<uint32_t*>(&v);
    u = __shfl_xor_sync(0xffffffffu, u, m);
    return *reinterpret_cast<__half2*>(&u);
}

// ---------------------------------------------------------------------------
// Prep: blocks [0,1024): drug/protein fp32 -> f16
//       blocks [1024,3072): W[k][n] fp32 -> Wt[n][k] f16 (W_d scaled by 1/16)
// ---------------------------------------------------------------------------
__global__ __launch_bounds__(256) void prep_kernel(
    const float* __restrict__ drug, const float* __restrict__ protein,
    const float* __restrict__ Wd, const float* __restrict__ Wp)
{
    __shared__ float t[32][33];
    int bid = blockIdx.x, tid = threadIdx.x;
    if (bid < 1024) {
        int i = bid * 256 + tid;                      // < BSZ*DEF/4
        float4 v = ((const float4*)drug)[i];
        __half2* d0 = (__half2*)g_abf[0];
        d0[i * 2]     = __floats2half2_rn(v.x, v.y);
        d0[i * 2 + 1] = __floats2half2_rn(v.z, v.w);
        float4 w = ((const float4*)protein)[i];
        __half2* d1 = (__half2*)g_abf[1];
        d1[i * 2]     = __floats2half2_rn(w.x, w.y);
        d1[i * 2 + 1] = __floats2half2_rn(w.z, w.w);
        return;
    }
    int wb = bid - 1024;                              // 0..2047
    int z = wb >> 10;
    int r = wb & 1023;
    int n0 = (r & 127) * 32, k0 = (r >> 7) * 32;
    const float* W = z ? Wp : Wd;
    float scale = z ? 1.0f : 0.0625f;
    int tx = tid & 31, ty = tid >> 5;                 // (32, 8)
#pragma unroll
    for (int q = 0; q < 4; q++)
        t[ty + q * 8][tx] = W[(size_t)(k0 + ty + q * 8) * NF + n0 + tx];
    __syncthreads();
#pragma unroll
    for (int q = 0; q < 4; q++)
        g_wbf[z][(size_t)(n0 + ty + q * 8) * DEF + k0 + tx] =
            __float2half(t[tx][ty + q * 8] * scale);
}

// ---------------------------------------------------------------------------
// HMMA GEMM (f16 accumulators, 2x rate): g_att[z][128x128] = relu(A@Wt^T + b)
// 256 thr (8 warps, warp tile 64x32). K = 4 chunks of 64, 2-stage cp.async
// pipeline, 64KB smem -> 2 CTAs/SM. Epilogue staged through smem (STG.128).
// ---------------------------------------------------------------------------
#define GSMEM 65536

__global__ __launch_bounds__(256, 2) void gemm_tc_kernel(const float* __restrict__ b_d,
                                                         const float* __restrict__ b_p)
{
    extern __shared__ __align__(16) char dsm[];       // stage s: A @ s*32768, B @ s*32768+16384
    __shared__ __half2 bias2[64];

    const int tid = threadIdx.x, lane = tid & 31, w = tid >> 5;
    const int wm = w >> 2, wn = w & 3;                // 2x4 warp grid
    const int Nb = blockIdx.x * 128, Mb = blockIdx.y * 128, z = blockIdx.z;
    uint32_t sbase = smem_u32(dsm);

    const __half* Ag = g_abf[z];
    const __half* Bg = g_wbf[z];
    if (tid < 64) {
        float s = z ? 1.0f : 0.0625f;
        const float* bias = z ? b_p : b_d;
        bias2[tid] = __floats2half2_rn(bias[Nb + 2 * tid] * s, bias[Nb + 2 * tid + 1] * s);
    }

    auto load_chunk = [&](int ch, int st) {
        uint32_t aB = sbase + st * 32768;
        uint32_t bB = aB + 16384;
#pragma unroll
        for (int j = 0; j < 4; j++) {
            int idx = tid + j * 256;                   // 0..1023
            int r = idx >> 3, c = idx & 7;
            uint32_t sw = (uint32_t)(r * 128 + ((c ^ (r & 7)) << 4));
            cp16(aB + sw, Ag + (size_t)(Mb + r) * DEF + ch * 64 + c * 8);
            cp16(bB + sw, Bg + (size_t)(Nb + r) * DEF + ch * 64 + c * 8);
        }
        CP_COMMIT();
    };

    load_chunk(0, 0);
    load_chunk(1, 1);

    uint32_t acc[4][4][2];
#pragma unroll
    for (int mf = 0; mf < 4; mf++)
#pragma unroll
        for (int nf = 0; nf < 4; nf++) { acc[mf][nf][0] = 0u; acc[mf][nf][1] = 0u; }

#pragma unroll
    for (int ch = 0; ch < 4; ch++) {
        if (ch == 3) { CP_WAIT(0); } else { CP_WAIT(1); }
        __syncthreads();
        uint32_t aBase = sbase + (ch & 1) * 32768;
        uint32_t bBase = aBase + 16384;
#pragma unroll
        for (int ks = 0; ks < 4; ks++) {
            uint32_t a[4][4];
#pragma unroll
            for (int mf = 0; mf < 4; mf++) {
                int r  = wm * 64 + mf * 16 + (lane & 7) + 8 * ((lane >> 3) & 1);
                int kc = ks * 2 + (lane >> 4);
                ldsm_x4(a[mf], aBase + r * 128 + ((kc ^ (r & 7)) << 4));
            }
            uint32_t bq[2][4];
#pragma unroll
            for (int g = 0; g < 2; g++) {
                int nr = wn * 32 + g * 16 + (lane & 7) + 8 * ((lane >> 4) & 1);
                int kc = ks * 2 + ((lane >> 3) & 1);
                ldsm_x4(bq[g], bBase + nr * 128 + ((kc ^ (nr & 7)) << 4));
            }
#pragma unroll
            for (int mf = 0; mf < 4; mf++)
#pragma unroll
                for (int nf = 0; nf < 4; nf++)
                    mma_h16_acc(acc[mf][nf], a[mf],
                                bq[nf >> 1][(nf & 1) * 2], bq[nf >> 1][(nf & 1) * 2 + 1]);
        }
        __syncthreads();
        if (ch + 2 < 4) load_chunk(ch + 2, ch & 1);
    }

    // epilogue: bias + relu in half2, staged via smem (XOR-swizzled), STG.128
    const __half2 z2 = __float2half2_rn(0.0f);
#pragma unroll
    for (int mf = 0; mf < 4; mf++) {
        int r0 = wm * 64 + mf * 16 + (lane >> 2);
#pragma unroll
        for (int nf = 0; nf < 4; nf++) {
            int u = wn * 4 + nf;                       // 16B unit within 256B row
            __half2 b2 = bias2[u * 4 + (lane & 3)];
            __half2 h0 = __hmax2(__hadd2(*(__half2*)&acc[mf][nf][0], b2), z2);
            __half2 h1 = __hmax2(__hadd2(*(__half2*)&acc[mf][nf][1], b2), z2);
            uint32_t a0 = sbase + r0 * 256 + ((u ^ (r0 & 7)) << 4) + 4 * (lane & 3);
            int r1 = r0 + 8;
            uint32_t a1 = sbase + r1 * 256 + ((u ^ (r1 & 7)) << 4) + 4 * (lane & 3);
            asm volatile("st.shared.b32 [%0], %1;" :: "r"(a0), "r"(*(uint32_t*)&h0) : "memory");
            asm volatile("st.shared.b32 [%0], %1;" :: "r"(a1), "r"(*(uint32_t*)&h1) : "memory");
        }
    }
    __syncthreads();
#pragma unroll
    for (int p = 0; p < 8; p++) {
        int g = tid + p * 256;                         // 0..2047 16B units
        int row = g >> 4, u = g & 15;
        uint4 v;
        uint32_t ad = sbase + row * 256 + ((u ^ (row & 7)) << 4);
        asm volatile("ld.shared.v4.u32 {%0,%1,%2,%3}, [%4];"
                     : "=r"(v.x), "=r"(v.y), "=r"(v.z), "=r"(v.w) : "r"(ad));
        *(uint4*)&g_att[z][(size_t)(Mb + row) * NF + Nb + u * 8] = v;
    }
}

// ---------------------------------------------------------------------------
// Interaction: per-sample S = D(scaled) @ P via f16-accumulator HMMA (K=16).
// ---------------------------------------------------------------------------
__global__ __launch_bounds__(256) void interact_kernel(
    const float* __restrict__ drug, const float* __restrict__ protein,
    float* __restrict__ out)
{
    __shared__ __align__(16) char Dsm[256 * 48];      // D rows stride 48B (32B data + pad)
    __shared__ __align__(16) char Psm[16 * 512];      // P [16][256] f16, XOR-swizzled
    __shared__ __half2 colpart[8][128];
    __shared__ float rowsum[256];

    const int b = blockIdx.x, tid = threadIdx.x, lane = tid & 31, w = tid >> 5;
    uint32_t sD = smem_u32(Dsm), sP = smem_u32(Psm);
    const __half* Drow = g_att[0] + (size_t)b * NF;
    const __half* Prow = g_att[1] + (size_t)b * NF;

#pragma unroll
    for (int j = 0; j < 2; j++) {
        int idx = tid + j * 256;                       // 0..511, 16B chunks
        int r = idx >> 1, c = idx & 1;
        cp16(sD + r * 48 + c * 16, Drow + idx * 8);
        int h = idx >> 5, c2 = idx & 31;
        cp16(sP + h * 512 + ((c2 ^ (h & 7)) << 4), Prow + idx * 8);
    }
    CP_COMMIT(); CP_WAIT(0); __syncthreads();

    uint32_t a[2][4];
#pragma unroll
    for (int mf = 0; mf < 2; mf++) {
        int r  = w * 32 + mf * 16 + (lane & 7) + 8 * ((lane >> 3) & 1);
        int kc = lane >> 4;
        ldsm_x4(a[mf], sD + r * 48 + kc * 16);
    }

    __half2 zero2 = __float2half2_rn(0.0f);
    __half2 rowp[4] = {zero2, zero2, zero2, zero2};

#pragma unroll
    for (int it = 0; it < 16; it++) {
        int n0 = it * 16;
        uint32_t bq[4];
        {
            int h = (lane & 7) + 8 * ((lane >> 3) & 1);
            int n = n0 + 8 * (lane >> 4);
            ldsm_x4t(bq, sP + h * 512 + (((n >> 3) ^ (h & 7)) << 4));
        }
        __half2 cp0 = zero2, cp1 = zero2;
#pragma unroll
        for (int mf = 0; mf < 2; mf++) {
            uint32_t d0[2];
            mma_h16(d0, a[mf], bq[0], bq[1]);          // cols n0 + 2q
            __half2 tA = tanh_h2(d0[0]);
            __half2 tB = tanh_h2(d0[1]);
            rowp[mf * 2 + 0] = __hadd2(rowp[mf * 2 + 0], tA);
            rowp[mf * 2 + 1] = __hadd2(rowp[mf * 2 + 1], tB);
            cp0 = __hadd2(cp0, __hadd2(tA, tB));

            uint32_t d1[2];
            mma_h16(d1, a[mf], bq[2], bq[3]);          // cols n0 + 8 + 2q
            tA = tanh_h2(d1[0]);
            tB = tanh_h2(d1[1]);
            rowp[mf * 2 + 0] = __hadd2(rowp[mf * 2 + 0], tA);
            rowp[mf * 2 + 1] = __hadd2(rowp[mf * 2 + 1], tB);
            cp1 = __hadd2(cp1, __hadd2(tA, tB));
        }
        cp0 = __hadd2(cp0, shfl_h2(cp0, 4));
        cp0 = __hadd2(cp0, shfl_h2(cp0, 8));
        cp0 = __hadd2(cp0, shfl_h2(cp0, 16));
        cp1 = __hadd2(cp1, shfl_h2(cp1, 4));
        cp1 = __hadd2(cp1, shfl_h2(cp1, 8));
        cp1 = __hadd2(cp1, shfl_h2(cp1, 16));
        if (lane < 4) {
            colpart[w][(n0 >> 1) + lane]     = cp0;
            colpart[w][(n0 >> 1) + 4 + lane] = cp1;
        }
    }

#pragma unroll
    for (int s = 0; s < 4; s++) {
        __half2 v = rowp[s];
        v = __hadd2(v, shfl_h2(v, 1));
        v = __hadd2(v, shfl_h2(v, 2));
        if ((lane & 3) == 0) {
            int row = w * 32 + (s >> 1) * 16 + (s & 1) * 8 + (lane >> 2);
            rowsum[row] = __low2float(v) + __high2float(v);
        }
    }
    __syncthreads();

    size_t o = (size_t)b * DEF + tid;
    out[o] = drug[o] * tanh_fast(rowsum[tid]);

    if (tid < 128) {
        float c0 = 0.0f, c1 = 0.0f;
#pragma unroll
        for (int ww = 0; ww < 8; ww++) {
            __half2 v = colpart[ww][tid];
            c0 += __low2float(v);
            c1 += __high2float(v);
        }
        size_t base2 = (size_t)BSZ * DEF + (size_t)b * DEF + 2 * tid;
        out[base2]     = protein[(size_t)b * DEF + 2 * tid]     * tanh_fast(c0);
        out[base2 + 1] = protein[(size_t)b * DEF + 2 * tid + 1] * tanh_fast(c1);
    }
}

// ---------------------------------------------------------------------------
extern "C" void kernel_launch(void* const* d_in, const int* in_sizes, int n_in,
                              void* d_out, int out_size)
{
    const float* drug    = (const float*)d_in[0];
    const float* protein = (const float*)d_in[1];
    const float* W_d     = (const float*)d_in[2];
    const float* b_d     = (const float*)d_in[3];
    const float* W_p     = (const float*)d_in[4];
    const float* b_p     = (const float*)d_in[5];
    float* out = (float*)d_out;

    cudaFuncSetAttribute(gemm_tc_kernel, cudaFuncAttributeMaxDynamicSharedMemorySize, GSMEM);

    prep_kernel<<<3072, 256>>>(drug, protein, W_d, W_p);
    gemm_tc_kernel<<<dim3(NF / 128, BSZ / 128, 2), 256, GSMEM>>>(b_d, b_p);
    interact_kernel<<<BSZ, 256>>>(drug, protein, out);
}